// round 1
// baseline (speedup 1.0000x reference)
#include <cuda_runtime.h>
#include <cuda_bf16.h>

// Problem constants
#define BATCH 8
#define HH 256
#define WW 256
#define HW (HH*WW)          // 65536
#define BHW (BATCH*HW)      // 524288

// Output plane offsets (tuple: outputs, H, C_new, V, V_hat)
#define OFF_OUT 0
#define OFF_H   (BHW)           // 524288
#define OFF_C   (2*BHW)         // 1048576  (size 2*BHW)
#define OFF_V   (4*BHW)         // 2097152
#define OFF_VH  (5*BHW)         // 2621440

// Scratch activations (device globals: allocation-free)
static __device__ float g_vs[BHW];                    // V / sf
static __device__ float g_h1[BATCH*32*HW];            // after conv1+relu
static __device__ float g_h2[BATCH*64*HW];            // after conv2+relu
static __device__ float g_h3[BATCH*32*HW];            // after conv3+relu

// ---------------------------------------------------------------------------
// Elementwise: C_new, V, H (with Laplacian), and V/sf scratch
// ---------------------------------------------------------------------------
__global__ void ew_kernel(const float* __restrict__ inputs,
                          const float* __restrict__ H0,
                          const float* __restrict__ C0,
                          const float* __restrict__ c2p,
                          const float* __restrict__ sfp,
                          float* __restrict__ out)
{
    int i = blockIdx.x * blockDim.x + threadIdx.x;
    if (i >= BHW) return;
    int x = i & (WW-1);
    int y = (i >> 8) & (HH-1);
    int b = i >> 16;
    int p = y*WW + x;

    float in = inputs[i];
    float h0 = H0[i];
    float c0 = C0[(b*2)*HW + p];
    float c2 = c2p[0];
    float sf = sfp[0];

    float V = in - h0;

    float up = (y > 0)     ? inputs[i - WW] : 0.f;
    float dn = (y < HH-1)  ? inputs[i + WW] : 0.f;
    float lf = (x > 0)     ? inputs[i - 1]  : 0.f;
    float rt = (x < WW-1)  ? inputs[i + 1]  : 0.f;
    float lap = up + dn + lf + rt - 4.f*in;

    float Hv = 2.f*in - c0 + c2*lap;

    out[OFF_H + i]                 = Hv;
    out[OFF_C + (b*2)*HW + p]      = in;   // C_new[:,0]
    out[OFF_C + (b*2)*HW + HW + p] = c0;   // C_new[:,1]
    out[OFF_V + i]                 = V;
    g_vs[i] = V / sf;
}

// ---------------------------------------------------------------------------
// Generic 3x3 SAME conv, NCHW, tiled.
// Block: 16x16 threads. Output tile: 16 rows x 32 cols (2 px per thread in x).
// SMEM: weights [COUT*CIN*9] + input tile chunk [CHUNK*18*34].
// ---------------------------------------------------------------------------
template<int CIN, int COUT, int CHUNK, bool RELU>
__global__ __launch_bounds__(256, 1)
void conv3x3_kernel(const float* __restrict__ in,
                    const float* __restrict__ w,
                    const float* __restrict__ bias,
                    float* __restrict__ out)
{
    extern __shared__ float smem[];
    float* sw  = smem;                    // COUT*CIN*9
    float* sin_ = smem + COUT*CIN*9;      // CHUNK*18*34

    const int tx = threadIdx.x;           // 0..15
    const int ty = threadIdx.y;           // 0..15
    const int tid = ty*16 + tx;

    const int bx = blockIdx.x * 32;
    const int by = blockIdx.y * 16;
    const int b  = blockIdx.z;

    // load weights
    const int NW = COUT*CIN*9;
    for (int t = tid; t < NW; t += 256) sw[t] = w[t];

    float acc0[COUT], acc1[COUT];
#pragma unroll
    for (int co = 0; co < COUT; co++) {
        float bv = bias[co];
        acc0[co] = bv;
        acc1[co] = bv;
    }

    const int ox = bx + 2*tx;
    const int oy = by + ty;

    for (int cc = 0; cc < CIN; cc += CHUNK) {
        __syncthreads();
        // load input tile chunk with halo (18 rows x 34 cols), zero-padded
        const int TILE = CHUNK * 18 * 34;
        for (int t = tid; t < TILE; t += 256) {
            int c  = t / (18*34);
            int r  = t % (18*34);
            int iy = r / 34;
            int ix = r % 34;
            int gy = by + iy - 1;
            int gx = bx + ix - 1;
            float v = 0.f;
            if (gy >= 0 && gy < HH && gx >= 0 && gx < WW)
                v = in[((size_t)(b*CIN + cc + c)*HH + gy)*WW + gx];
            sin_[t] = v;
        }
        __syncthreads();

        for (int c = 0; c < CHUNK; c++) {
            const float* srow = &sin_[c*18*34];
            const float* wp0  = &sw[(cc + c)*9];
#pragma unroll
            for (int ky = 0; ky < 3; ky++) {
#pragma unroll
                for (int kx = 0; kx < 3; kx++) {
                    float v0 = srow[(ty+ky)*34 + 2*tx + kx];
                    float v1 = srow[(ty+ky)*34 + 2*tx + kx + 1];
                    const float* wp = wp0 + ky*3 + kx;
#pragma unroll
                    for (int co = 0; co < COUT; co++) {
                        float wv = wp[co*CIN*9];
                        acc0[co] = fmaf(wv, v0, acc0[co]);
                        acc1[co] = fmaf(wv, v1, acc1[co]);
                    }
                }
            }
        }
    }

    // write (float2: ox is even)
#pragma unroll
    for (int co = 0; co < COUT; co++) {
        float r0 = acc0[co], r1 = acc1[co];
        if (RELU) { r0 = fmaxf(r0, 0.f); r1 = fmaxf(r1, 0.f); }
        size_t base = ((size_t)(b*COUT + co)*HH + oy)*WW + ox;
        *reinterpret_cast<float2*>(&out[base]) = make_float2(r0, r1);
    }
}

// ---------------------------------------------------------------------------
// conv4 (32 -> 1) + epilogue: V_hat = sf*o ; outputs = H + V_hat
// ---------------------------------------------------------------------------
__global__ __launch_bounds__(256, 1)
void conv4_kernel(const float* __restrict__ in,      // g_h3 [B,32,H,W]
                  const float* __restrict__ w,       // [1,32,3,3]
                  const float* __restrict__ bias,    // [1]
                  const float* __restrict__ sfp,
                  float* __restrict__ out)
{
    extern __shared__ float smem[];
    float* sw  = smem;            // 288
    float* sin_ = smem + 288;     // 32*18*34

    const int tx = threadIdx.x;
    const int ty = threadIdx.y;
    const int tid = ty*16 + tx;

    const int bx = blockIdx.x * 32;
    const int by = blockIdx.y * 16;
    const int b  = blockIdx.z;

    for (int t = tid; t < 288; t += 256) sw[t] = w[t];

    const int TILE = 32 * 18 * 34;
    for (int t = tid; t < TILE; t += 256) {
        int c  = t / (18*34);
        int r  = t % (18*34);
        int iy = r / 34;
        int ix = r % 34;
        int gy = by + iy - 1;
        int gx = bx + ix - 1;
        float v = 0.f;
        if (gy >= 0 && gy < HH && gx >= 0 && gx < WW)
            v = in[((size_t)(b*32 + c)*HH + gy)*WW + gx];
        sin_[t] = v;
    }
    __syncthreads();

    float acc0 = bias[0];
    float acc1 = bias[0];
    for (int c = 0; c < 32; c++) {
        const float* srow = &sin_[c*18*34];
        const float* wp   = &sw[c*9];
#pragma unroll
        for (int ky = 0; ky < 3; ky++) {
#pragma unroll
            for (int kx = 0; kx < 3; kx++) {
                float wv = wp[ky*3 + kx];
                float v0 = srow[(ty+ky)*34 + 2*tx + kx];
                float v1 = srow[(ty+ky)*34 + 2*tx + kx + 1];
                acc0 = fmaf(wv, v0, acc0);
                acc1 = fmaf(wv, v1, acc1);
            }
        }
    }

    float sf = sfp[0];
    int oy = by + ty;
    int ox = bx + 2*tx;
    size_t i = (size_t)b*HW + oy*WW + ox;
    float vh0 = acc0 * sf;
    float vh1 = acc1 * sf;
    float h0v = out[OFF_H + i];
    float h1v = out[OFF_H + i + 1];
    *reinterpret_cast<float2*>(&out[OFF_VH  + i]) = make_float2(vh0, vh1);
    *reinterpret_cast<float2*>(&out[OFF_OUT + i]) = make_float2(h0v + vh0, h1v + vh1);
}

// ---------------------------------------------------------------------------
extern "C" void kernel_launch(void* const* d_in, const int* in_sizes, int n_in,
                              void* d_out, int out_size)
{
    const float* inputs = (const float*)d_in[0];
    const float* H0     = (const float*)d_in[1];
    const float* C0     = (const float*)d_in[2];
    const float* c2     = (const float*)d_in[3];
    const float* sf     = (const float*)d_in[4];
    const float* w1     = (const float*)d_in[5];
    const float* b1     = (const float*)d_in[6];
    const float* w2     = (const float*)d_in[7];
    const float* b2     = (const float*)d_in[8];
    const float* w3     = (const float*)d_in[9];
    const float* b3     = (const float*)d_in[10];
    const float* w4     = (const float*)d_in[11];
    const float* b4     = (const float*)d_in[12];
    float* out = (float*)d_out;

    void *vs_p, *h1_p, *h2_p, *h3_p;
    cudaGetSymbolAddress(&vs_p, g_vs);
    cudaGetSymbolAddress(&h1_p, g_h1);
    cudaGetSymbolAddress(&h2_p, g_h2);
    cudaGetSymbolAddress(&h3_p, g_h3);
    float* vs = (float*)vs_p;
    float* h1 = (float*)h1_p;
    float* h2 = (float*)h2_p;
    float* h3 = (float*)h3_p;

    // shared memory sizes (bytes)
    constexpr int SM1 = (32*1*9  + 1 *18*34) * 4;   // conv1
    constexpr int SM2 = (64*32*9 + 32*18*34) * 4;   // conv2 = 152064
    constexpr int SM3 = (32*64*9 + 32*18*34) * 4;   // conv3 = 152064
    constexpr int SM4 = (288     + 32*18*34) * 4;   // conv4 = 79488

    cudaFuncSetAttribute(conv3x3_kernel<1,32,1,true>,
                         cudaFuncAttributeMaxDynamicSharedMemorySize, SM1);
    cudaFuncSetAttribute(conv3x3_kernel<32,64,32,true>,
                         cudaFuncAttributeMaxDynamicSharedMemorySize, SM2);
    cudaFuncSetAttribute(conv3x3_kernel<64,32,32,true>,
                         cudaFuncAttributeMaxDynamicSharedMemorySize, SM3);
    cudaFuncSetAttribute(conv4_kernel,
                         cudaFuncAttributeMaxDynamicSharedMemorySize, SM4);

    // 1) elementwise
    ew_kernel<<<(BHW + 255)/256, 256>>>(inputs, H0, C0, c2, sf, out);

    dim3 blk(16, 16);
    dim3 grd(WW/32, HH/16, BATCH);   // (8,16,8)

    // 2) conv1: 1->32, relu
    conv3x3_kernel<1,32,1,true><<<grd, blk, SM1>>>(vs, w1, b1, h1);
    // 3) conv2: 32->64, relu
    conv3x3_kernel<32,64,32,true><<<grd, blk, SM2>>>(h1, w2, b2, h2);
    // 4) conv3: 64->32, relu
    conv3x3_kernel<64,32,32,true><<<grd, blk, SM3>>>(h2, w3, b3, h3);
    // 5) conv4 + epilogue
    conv4_kernel<<<grd, blk, SM4>>>(h3, w4, b4, sf, out);
}

// round 2
// speedup vs baseline: 1.0401x; 1.0401x over previous
#include <cuda_runtime.h>
#include <cuda_bf16.h>

// Problem constants
#define BATCH 8
#define HH 256
#define WW 256
#define HW (HH*WW)          // 65536
#define BHW (BATCH*HW)      // 524288

// Output plane offsets (tuple: outputs, H, C_new, V, V_hat)
#define OFF_OUT 0
#define OFF_H   (BHW)
#define OFF_C   (2*BHW)
#define OFF_V   (4*BHW)
#define OFF_VH  (5*BHW)

// Scratch activations (device globals: allocation-free)
static __device__ float g_vs[BHW];
static __device__ float g_h1[BATCH*32*HW];
static __device__ float g_h2[BATCH*64*HW];
static __device__ float g_h3[BATCH*32*HW];

// ---------------------------------------------------------------------------
// Packed f32x2 helpers
// ---------------------------------------------------------------------------
__device__ __forceinline__ unsigned long long pack2(float lo, float hi) {
    unsigned long long r;
    asm("mov.b64 %0, {%1, %2};" : "=l"(r) : "f"(lo), "f"(hi));
    return r;
}
__device__ __forceinline__ void unpack2(unsigned long long v, float& lo, float& hi) {
    asm("mov.b64 {%0, %1}, %2;" : "=f"(lo), "=f"(hi) : "l"(v));
}
__device__ __forceinline__ void ffma2(unsigned long long& d,
                                      unsigned long long a,
                                      unsigned long long b) {
    asm("fma.rn.f32x2 %0, %1, %2, %0;" : "+l"(d) : "l"(a), "l"(b));
}

// ---------------------------------------------------------------------------
// Elementwise: C_new, V, H (with Laplacian), and V/sf scratch
// ---------------------------------------------------------------------------
__global__ void ew_kernel(const float* __restrict__ inputs,
                          const float* __restrict__ H0,
                          const float* __restrict__ C0,
                          const float* __restrict__ c2p,
                          const float* __restrict__ sfp,
                          float* __restrict__ out)
{
    int i = blockIdx.x * blockDim.x + threadIdx.x;
    if (i >= BHW) return;
    int x = i & (WW-1);
    int y = (i >> 8) & (HH-1);
    int b = i >> 16;
    int p = y*WW + x;

    float in = inputs[i];
    float h0 = H0[i];
    float c0 = C0[(b*2)*HW + p];
    float c2 = c2p[0];
    float sf = sfp[0];

    float V = in - h0;

    float up = (y > 0)     ? inputs[i - WW] : 0.f;
    float dn = (y < HH-1)  ? inputs[i + WW] : 0.f;
    float lf = (x > 0)     ? inputs[i - 1]  : 0.f;
    float rt = (x < WW-1)  ? inputs[i + 1]  : 0.f;
    float lap = up + dn + lf + rt - 4.f*in;

    float Hv = 2.f*in - c0 + c2*lap;

    out[OFF_H + i]                 = Hv;
    out[OFF_C + (b*2)*HW + p]      = in;
    out[OFF_C + (b*2)*HW + HW + p] = c0;
    out[OFF_V + i]                 = V;
    g_vs[i] = V / sf;
}

// ---------------------------------------------------------------------------
// 3x3 SAME conv, NCHW, tiled, FFMA2 over co-pairs.
// Block: 16x16 threads, output tile 16 rows x 32 cols (2 px per thread).
// Each block computes COUT_BLK output channels (co split via blockIdx.z).
// SMEM: transposed weights [CIN*9][COUT_BLK] + input chunk [CHUNK][18][34].
// ---------------------------------------------------------------------------
template<int CIN, int COUT_BLK, int NSPLIT, int CHUNK, bool RELU>
__global__ __launch_bounds__(256, 2)
void conv3x3_p2_kernel(const float* __restrict__ in,
                       const float* __restrict__ w,
                       const float* __restrict__ bias,
                       float* __restrict__ out)
{
    extern __shared__ float smem[];
    float* sw  = smem;                       // CIN*9*COUT_BLK (transposed)
    float* sin_ = smem + CIN*9*COUT_BLK;     // CHUNK*18*34

    const int tx = threadIdx.x;              // 0..15
    const int ty = threadIdx.y;              // 0..15
    const int tid = ty*16 + tx;

    const int bx = blockIdx.x * 32;
    const int by = blockIdx.y * 16;
    const int bz = blockIdx.z;
    const int b  = bz / NSPLIT;
    const int coStart = (bz % NSPLIT) * COUT_BLK;

    // Load + transpose weights: w[co][ci][tap] -> sw[(ci*9+tap)*COUT_BLK + co]
    const int NW = COUT_BLK * CIN * 9;
    for (int t = tid; t < NW; t += 256) {
        int co  = t / (CIN*9);
        int rem = t - co*(CIN*9);
        sw[rem*COUT_BLK + co] = w[(size_t)(coStart + co)*(CIN*9) + rem];
    }

    // Packed accumulators over co-pairs: accP0 = pixel0, accP1 = pixel1
    unsigned long long accP0[COUT_BLK/2], accP1[COUT_BLK/2];
#pragma unroll
    for (int j = 0; j < COUT_BLK/2; j++) {
        unsigned long long bv = pack2(bias[coStart + 2*j], bias[coStart + 2*j + 1]);
        accP0[j] = bv;
        accP1[j] = bv;
    }

    for (int cc = 0; cc < CIN; cc += CHUNK) {
        __syncthreads();
        // Load input chunk with halo (18 rows x 34 cols per channel)
#pragma unroll 1
        for (int c = 0; c < CHUNK; c++) {
            const float* gch = &in[((size_t)(b*CIN + cc + c)*HH)*WW];
            float* sch = &sin_[c*18*34];
            for (int r = tid; r < 18*34; r += 256) {
                int iy = r / 34;
                int ix = r - iy*34;
                int gy = by + iy - 1;
                int gx = bx + ix - 1;
                float v = 0.f;
                if (gy >= 0 && gy < HH && gx >= 0 && gx < WW)
                    v = gch[gy*WW + gx];
                sch[r] = v;
            }
        }
        __syncthreads();

#pragma unroll 1
        for (int c = 0; c < CHUNK; c++) {
#pragma unroll
            for (int ky = 0; ky < 3; ky++) {
                const float* srow = &sin_[(c*18 + ty + ky)*34 + 2*tx];
                float2 f01 = *reinterpret_cast<const float2*>(&srow[0]);
                float2 f23 = *reinterpret_cast<const float2*>(&srow[2]);
                unsigned long long d0 = pack2(f01.x, f01.x);
                unsigned long long d1 = pack2(f01.y, f01.y);
                unsigned long long d2 = pack2(f23.x, f23.x);
                unsigned long long d3 = pack2(f23.y, f23.y);
                const int tapBase = ((cc + c)*3 + ky)*3;
#pragma unroll
                for (int kx = 0; kx < 3; kx++) {
                    unsigned long long a0 = (kx == 0) ? d0 : (kx == 1) ? d1 : d2;
                    unsigned long long a1 = (kx == 0) ? d1 : (kx == 1) ? d2 : d3;
                    const ulonglong2* wrow = reinterpret_cast<const ulonglong2*>(
                        &sw[(tapBase + kx)*COUT_BLK]);
#pragma unroll
                    for (int j = 0; j < COUT_BLK/4; j++) {
                        ulonglong2 wv = wrow[j];
                        ffma2(accP0[2*j],   a0, wv.x);
                        ffma2(accP0[2*j+1], a0, wv.y);
                        ffma2(accP1[2*j],   a1, wv.x);
                        ffma2(accP1[2*j+1], a1, wv.y);
                    }
                }
            }
        }
    }

    // Write out (ox even -> float2 stores)
    const int ox = bx + 2*tx;
    const int oy = by + ty;
    const int COUT_TOT = COUT_BLK * NSPLIT;
#pragma unroll
    for (int j = 0; j < COUT_BLK/2; j++) {
        float p0lo, p0hi, p1lo, p1hi;
        unpack2(accP0[j], p0lo, p0hi);
        unpack2(accP1[j], p1lo, p1hi);
        if (RELU) {
            p0lo = fmaxf(p0lo, 0.f); p0hi = fmaxf(p0hi, 0.f);
            p1lo = fmaxf(p1lo, 0.f); p1hi = fmaxf(p1hi, 0.f);
        }
        int co = coStart + 2*j;
        size_t base0 = ((size_t)(b*COUT_TOT + co)*HH + oy)*WW + ox;
        size_t base1 = base0 + (size_t)HH*WW;
        *reinterpret_cast<float2*>(&out[base0]) = make_float2(p0lo, p1lo);
        *reinterpret_cast<float2*>(&out[base1]) = make_float2(p0hi, p1hi);
    }
}

// ---------------------------------------------------------------------------
// conv4 (32 -> 1) + epilogue: V_hat = sf*o ; outputs = H + V_hat
// ---------------------------------------------------------------------------
__global__ __launch_bounds__(256, 2)
void conv4_kernel(const float* __restrict__ in,      // g_h3 [B,32,H,W]
                  const float* __restrict__ w,       // [1,32,3,3]
                  const float* __restrict__ bias,    // [1]
                  const float* __restrict__ sfp,
                  float* __restrict__ out)
{
    extern __shared__ float smem[];
    float* sw  = smem;            // 288
    float* sin_ = smem + 288;     // 8*18*34 (chunked)

    const int tx = threadIdx.x;
    const int ty = threadIdx.y;
    const int tid = ty*16 + tx;

    const int bx = blockIdx.x * 32;
    const int by = blockIdx.y * 16;
    const int b  = blockIdx.z;

    for (int t = tid; t < 288; t += 256) sw[t] = w[t];

    // pixel-packed accumulator: (px0, px1)
    unsigned long long acc = pack2(bias[0], bias[0]);

    for (int cc = 0; cc < 32; cc += 8) {
        __syncthreads();
#pragma unroll 1
        for (int c = 0; c < 8; c++) {
            const float* gch = &in[((size_t)(b*32 + cc + c)*HH)*WW];
            float* sch = &sin_[c*18*34];
            for (int r = tid; r < 18*34; r += 256) {
                int iy = r / 34;
                int ix = r - iy*34;
                int gy = by + iy - 1;
                int gx = bx + ix - 1;
                float v = 0.f;
                if (gy >= 0 && gy < HH && gx >= 0 && gx < WW)
                    v = gch[gy*WW + gx];
                sch[r] = v;
            }
        }
        __syncthreads();

#pragma unroll 1
        for (int c = 0; c < 8; c++) {
#pragma unroll
            for (int ky = 0; ky < 3; ky++) {
                const float* srow = &sin_[(c*18 + ty + ky)*34 + 2*tx];
                float2 f01 = *reinterpret_cast<const float2*>(&srow[0]);
                float2 f23 = *reinterpret_cast<const float2*>(&srow[2]);
                const float* wp = &sw[(cc + c)*9 + ky*3];
                ffma2(acc, pack2(f01.x, f01.y), pack2(wp[0], wp[0]));
                ffma2(acc, pack2(f01.y, f23.x), pack2(wp[1], wp[1]));
                ffma2(acc, pack2(f23.x, f23.y), pack2(wp[2], wp[2]));
            }
        }
    }

    float a0, a1;
    unpack2(acc, a0, a1);
    float sf = sfp[0];
    int oy = by + ty;
    int ox = bx + 2*tx;
    size_t i = (size_t)b*HW + oy*WW + ox;
    float vh0 = a0 * sf;
    float vh1 = a1 * sf;
    float h0v = out[OFF_H + i];
    float h1v = out[OFF_H + i + 1];
    *reinterpret_cast<float2*>(&out[OFF_VH  + i]) = make_float2(vh0, vh1);
    *reinterpret_cast<float2*>(&out[OFF_OUT + i]) = make_float2(h0v + vh0, h1v + vh1);
}

// ---------------------------------------------------------------------------
extern "C" void kernel_launch(void* const* d_in, const int* in_sizes, int n_in,
                              void* d_out, int out_size)
{
    const float* inputs = (const float*)d_in[0];
    const float* H0     = (const float*)d_in[1];
    const float* C0     = (const float*)d_in[2];
    const float* c2     = (const float*)d_in[3];
    const float* sf     = (const float*)d_in[4];
    const float* w1     = (const float*)d_in[5];
    const float* b1     = (const float*)d_in[6];
    const float* w2     = (const float*)d_in[7];
    const float* b2     = (const float*)d_in[8];
    const float* w3     = (const float*)d_in[9];
    const float* b3     = (const float*)d_in[10];
    const float* w4     = (const float*)d_in[11];
    const float* b4     = (const float*)d_in[12];
    float* out = (float*)d_out;

    void *vs_p, *h1_p, *h2_p, *h3_p;
    cudaGetSymbolAddress(&vs_p, g_vs);
    cudaGetSymbolAddress(&h1_p, g_h1);
    cudaGetSymbolAddress(&h2_p, g_h2);
    cudaGetSymbolAddress(&h3_p, g_h3);
    float* vs = (float*)vs_p;
    float* h1 = (float*)h1_p;
    float* h2 = (float*)h2_p;
    float* h3 = (float*)h3_p;

    // conv1: CIN=1, COUT_BLK=32, NSPLIT=1, CHUNK=1
    constexpr int SM1 = (1*9*32   + 1*18*34) * 4;    //  3600 B
    // conv2: CIN=32, COUT_BLK=32, NSPLIT=2, CHUNK=8
    constexpr int SM2 = (32*9*32  + 8*18*34) * 4;    // 56448 B
    // conv3: CIN=64, COUT_BLK=32, NSPLIT=1, CHUNK=8
    constexpr int SM3 = (64*9*32  + 8*18*34) * 4;    // 93312 B
    // conv4
    constexpr int SM4 = (288      + 8*18*34) * 4;    // 20736 B

    cudaFuncSetAttribute(conv3x3_p2_kernel<1,32,1,1,true>,
                         cudaFuncAttributeMaxDynamicSharedMemorySize, SM1);
    cudaFuncSetAttribute(conv3x3_p2_kernel<32,32,2,8,true>,
                         cudaFuncAttributeMaxDynamicSharedMemorySize, SM2);
    cudaFuncSetAttribute(conv3x3_p2_kernel<64,32,1,8,true>,
                         cudaFuncAttributeMaxDynamicSharedMemorySize, SM3);
    cudaFuncSetAttribute(conv4_kernel,
                         cudaFuncAttributeMaxDynamicSharedMemorySize, SM4);

    // 1) elementwise
    ew_kernel<<<(BHW + 255)/256, 256>>>(inputs, H0, C0, c2, sf, out);

    dim3 blk(16, 16);

    // 2) conv1: 1->32, relu
    conv3x3_p2_kernel<1,32,1,1,true>
        <<<dim3(8,16,BATCH), blk, SM1>>>(vs, w1, b1, h1);
    // 3) conv2: 32->64, relu (co split across 2 blocks)
    conv3x3_p2_kernel<32,32,2,8,true>
        <<<dim3(8,16,BATCH*2), blk, SM2>>>(h1, w2, b2, h2);
    // 4) conv3: 64->32, relu
    conv3x3_p2_kernel<64,32,1,8,true>
        <<<dim3(8,16,BATCH), blk, SM3>>>(h2, w3, b3, h3);
    // 5) conv4 + epilogue
    conv4_kernel<<<dim3(8,16,BATCH), blk, SM4>>>(h3, w4, b4, sf, out);
}

// round 3
// speedup vs baseline: 1.1649x; 1.1201x over previous
#include <cuda_runtime.h>
#include <cuda_bf16.h>

// Problem constants
#define BATCH 8
#define HH 256
#define WW 256
#define HW (HH*WW)          // 65536
#define BHW (BATCH*HW)      // 524288

// Output plane offsets (tuple: outputs, H, C_new, V, V_hat)
#define OFF_OUT 0
#define OFF_H   (BHW)
#define OFF_C   (2*BHW)
#define OFF_V   (4*BHW)
#define OFF_VH  (5*BHW)

// Scratch activations (device globals: allocation-free)
static __device__ float g_vs[BHW];
static __device__ float g_h1[BATCH*32*HW];
static __device__ float g_h2[BATCH*64*HW];
static __device__ float g_h3[BATCH*32*HW];

// ---------------------------------------------------------------------------
// Packed f32x2 helpers
// ---------------------------------------------------------------------------
__device__ __forceinline__ unsigned long long pack2(float lo, float hi) {
    unsigned long long r;
    asm("mov.b64 %0, {%1, %2};" : "=l"(r) : "f"(lo), "f"(hi));
    return r;
}
__device__ __forceinline__ void unpack2(unsigned long long v, float& lo, float& hi) {
    asm("mov.b64 {%0, %1}, %2;" : "=f"(lo), "=f"(hi) : "l"(v));
}
__device__ __forceinline__ void ffma2(unsigned long long& d,
                                      unsigned long long a,
                                      unsigned long long b) {
    asm("fma.rn.f32x2 %0, %1, %2, %0;" : "+l"(d) : "l"(a), "l"(b));
}

// ---------------------------------------------------------------------------
// Elementwise: C_new, V, H (with Laplacian), and V/sf scratch
// ---------------------------------------------------------------------------
__global__ void ew_kernel(const float* __restrict__ inputs,
                          const float* __restrict__ H0,
                          const float* __restrict__ C0,
                          const float* __restrict__ c2p,
                          const float* __restrict__ sfp,
                          float* __restrict__ out)
{
    int i = blockIdx.x * blockDim.x + threadIdx.x;
    if (i >= BHW) return;
    int x = i & (WW-1);
    int y = (i >> 8) & (HH-1);
    int b = i >> 16;
    int p = y*WW + x;

    float in = inputs[i];
    float h0 = H0[i];
    float c0 = C0[(b*2)*HW + p];
    float c2 = c2p[0];
    float sf = sfp[0];

    float V = in - h0;

    float up = (y > 0)     ? inputs[i - WW] : 0.f;
    float dn = (y < HH-1)  ? inputs[i + WW] : 0.f;
    float lf = (x > 0)     ? inputs[i - 1]  : 0.f;
    float rt = (x < WW-1)  ? inputs[i + 1]  : 0.f;
    float lap = up + dn + lf + rt - 4.f*in;

    float Hv = 2.f*in - c0 + c2*lap;

    out[OFF_H + i]                 = Hv;
    out[OFF_C + (b*2)*HW + p]      = in;
    out[OFF_C + (b*2)*HW + HW + p] = c0;
    out[OFF_V + i]                 = V;
    g_vs[i] = V / sf;
}

// ---------------------------------------------------------------------------
// 3x3 SAME conv, NCHW, tiled, FFMA2 over co-pairs.
// Block: 16x16 threads, output tile 16 rows x 32 cols (2 px per thread).
// Each block computes COUT_BLK output channels (co split via blockIdx.z).
// SMEM: transposed weights [CIN*9][COUT_BLK] + input chunk [CHUNK][18][34].
// ---------------------------------------------------------------------------
template<int CIN, int COUT_BLK, int NSPLIT, int CHUNK, bool RELU>
__global__ __launch_bounds__(256, 2)
void conv3x3_p2_kernel(const float* __restrict__ in,
                       const float* __restrict__ w,
                       const float* __restrict__ bias,
                       float* __restrict__ out)
{
    extern __shared__ float smem[];
    float* sw  = smem;                       // CIN*9*COUT_BLK (transposed)
    float* sin_ = smem + CIN*9*COUT_BLK;     // CHUNK*18*34

    const int tx = threadIdx.x;              // 0..15
    const int ty = threadIdx.y;              // 0..15
    const int tid = ty*16 + tx;

    const int bx = blockIdx.x * 32;
    const int by = blockIdx.y * 16;
    const int bz = blockIdx.z;
    const int b  = bz / NSPLIT;
    const int coStart = (bz % NSPLIT) * COUT_BLK;

    // Load + transpose weights: w[co][ci][tap] -> sw[(ci*9+tap)*COUT_BLK + co]
    const int NW = COUT_BLK * CIN * 9;
    for (int t = tid; t < NW; t += 256) {
        int co  = t / (CIN*9);
        int rem = t - co*(CIN*9);
        sw[rem*COUT_BLK + co] = w[(size_t)(coStart + co)*(CIN*9) + rem];
    }

    // Packed accumulators over co-pairs: accP0 = pixel0, accP1 = pixel1
    unsigned long long accP0[COUT_BLK/2], accP1[COUT_BLK/2];
#pragma unroll
    for (int j = 0; j < COUT_BLK/2; j++) {
        unsigned long long bv = pack2(bias[coStart + 2*j], bias[coStart + 2*j + 1]);
        accP0[j] = bv;
        accP1[j] = bv;
    }

    for (int cc = 0; cc < CIN; cc += CHUNK) {
        __syncthreads();
        // Load input chunk with halo (18 rows x 34 cols per channel)
#pragma unroll 1
        for (int c = 0; c < CHUNK; c++) {
            const float* gch = &in[((size_t)(b*CIN + cc + c)*HH)*WW];
            float* sch = &sin_[c*18*34];
            for (int r = tid; r < 18*34; r += 256) {
                int iy = r / 34;
                int ix = r - iy*34;
                int gy = by + iy - 1;
                int gx = bx + ix - 1;
                float v = 0.f;
                if (gy >= 0 && gy < HH && gx >= 0 && gx < WW)
                    v = gch[gy*WW + gx];
                sch[r] = v;
            }
        }
        __syncthreads();

#pragma unroll 1
        for (int c = 0; c < CHUNK; c++) {
#pragma unroll
            for (int ky = 0; ky < 3; ky++) {
                const float* srow = &sin_[(c*18 + ty + ky)*34 + 2*tx];
                float2 f01 = *reinterpret_cast<const float2*>(&srow[0]);
                float2 f23 = *reinterpret_cast<const float2*>(&srow[2]);
                unsigned long long d0 = pack2(f01.x, f01.x);
                unsigned long long d1 = pack2(f01.y, f01.y);
                unsigned long long d2 = pack2(f23.x, f23.x);
                unsigned long long d3 = pack2(f23.y, f23.y);
                const int tapBase = ((cc + c)*3 + ky)*3;
#pragma unroll
                for (int kx = 0; kx < 3; kx++) {
                    unsigned long long a0 = (kx == 0) ? d0 : (kx == 1) ? d1 : d2;
                    unsigned long long a1 = (kx == 0) ? d1 : (kx == 1) ? d2 : d3;
                    const ulonglong2* wrow = reinterpret_cast<const ulonglong2*>(
                        &sw[(tapBase + kx)*COUT_BLK]);
#pragma unroll
                    for (int j = 0; j < COUT_BLK/4; j++) {
                        ulonglong2 wv = wrow[j];
                        ffma2(accP0[2*j],   a0, wv.x);
                        ffma2(accP0[2*j+1], a0, wv.y);
                        ffma2(accP1[2*j],   a1, wv.x);
                        ffma2(accP1[2*j+1], a1, wv.y);
                    }
                }
            }
        }
    }

    // Write out (ox even -> float2 stores)
    const int ox = bx + 2*tx;
    const int oy = by + ty;
    const int COUT_TOT = COUT_BLK * NSPLIT;
#pragma unroll
    for (int j = 0; j < COUT_BLK/2; j++) {
        float p0lo, p0hi, p1lo, p1hi;
        unpack2(accP0[j], p0lo, p0hi);
        unpack2(accP1[j], p1lo, p1hi);
        if (RELU) {
            p0lo = fmaxf(p0lo, 0.f); p0hi = fmaxf(p0hi, 0.f);
            p1lo = fmaxf(p1lo, 0.f); p1hi = fmaxf(p1hi, 0.f);
        }
        int co = coStart + 2*j;
        size_t base0 = ((size_t)(b*COUT_TOT + co)*HH + oy)*WW + ox;
        size_t base1 = base0 + (size_t)HH*WW;
        *reinterpret_cast<float2*>(&out[base0]) = make_float2(p0lo, p1lo);
        *reinterpret_cast<float2*>(&out[base1]) = make_float2(p0hi, p1hi);
    }
}

// ---------------------------------------------------------------------------
// conv4 (32 -> 1) + epilogue: V_hat = sf*o ; outputs = H + V_hat
// ---------------------------------------------------------------------------
__global__ __launch_bounds__(256, 2)
void conv4_kernel(const float* __restrict__ in,      // g_h3 [B,32,H,W]
                  const float* __restrict__ w,       // [1,32,3,3]
                  const float* __restrict__ bias,    // [1]
                  const float* __restrict__ sfp,
                  float* __restrict__ out)
{
    extern __shared__ float smem[];
    float* sw  = smem;            // 288
    float* sin_ = smem + 288;     // 8*18*34 (chunked)

    const int tx = threadIdx.x;
    const int ty = threadIdx.y;
    const int tid = ty*16 + tx;

    const int bx = blockIdx.x * 32;
    const int by = blockIdx.y * 16;
    const int b  = blockIdx.z;

    for (int t = tid; t < 288; t += 256) sw[t] = w[t];

    // pixel-packed accumulator: (px0, px1)
    unsigned long long acc = pack2(bias[0], bias[0]);

    for (int cc = 0; cc < 32; cc += 8) {
        __syncthreads();
#pragma unroll 1
        for (int c = 0; c < 8; c++) {
            const float* gch = &in[((size_t)(b*32 + cc + c)*HH)*WW];
            float* sch = &sin_[c*18*34];
            for (int r = tid; r < 18*34; r += 256) {
                int iy = r / 34;
                int ix = r - iy*34;
                int gy = by + iy - 1;
                int gx = bx + ix - 1;
                float v = 0.f;
                if (gy >= 0 && gy < HH && gx >= 0 && gx < WW)
                    v = gch[gy*WW + gx];
                sch[r] = v;
            }
        }
        __syncthreads();

#pragma unroll 1
        for (int c = 0; c < 8; c++) {
#pragma unroll
            for (int ky = 0; ky < 3; ky++) {
                const float* srow = &sin_[(c*18 + ty + ky)*34 + 2*tx];
                float2 f01 = *reinterpret_cast<const float2*>(&srow[0]);
                float2 f23 = *reinterpret_cast<const float2*>(&srow[2]);
                const float* wp = &sw[(cc + c)*9 + ky*3];
                ffma2(acc, pack2(f01.x, f01.y), pack2(wp[0], wp[0]));
                ffma2(acc, pack2(f01.y, f23.x), pack2(wp[1], wp[1]));
                ffma2(acc, pack2(f23.x, f23.y), pack2(wp[2], wp[2]));
            }
        }
    }

    float a0, a1;
    unpack2(acc, a0, a1);
    float sf = sfp[0];
    int oy = by + ty;
    int ox = bx + 2*tx;
    size_t i = (size_t)b*HW + oy*WW + ox;
    float vh0 = a0 * sf;
    float vh1 = a1 * sf;
    float h0v = out[OFF_H + i];
    float h1v = out[OFF_H + i + 1];
    *reinterpret_cast<float2*>(&out[OFF_VH  + i]) = make_float2(vh0, vh1);
    *reinterpret_cast<float2*>(&out[OFF_OUT + i]) = make_float2(h0v + vh0, h1v + vh1);
}

// ---------------------------------------------------------------------------
extern "C" void kernel_launch(void* const* d_in, const int* in_sizes, int n_in,
                              void* d_out, int out_size)
{
    const float* inputs = (const float*)d_in[0];
    const float* H0     = (const float*)d_in[1];
    const float* C0     = (const float*)d_in[2];
    const float* c2     = (const float*)d_in[3];
    const float* sf     = (const float*)d_in[4];
    const float* w1     = (const float*)d_in[5];
    const float* b1     = (const float*)d_in[6];
    const float* w2     = (const float*)d_in[7];
    const float* b2     = (const float*)d_in[8];
    const float* w3     = (const float*)d_in[9];
    const float* b3     = (const float*)d_in[10];
    const float* w4     = (const float*)d_in[11];
    const float* b4     = (const float*)d_in[12];
    float* out = (float*)d_out;

    void *vs_p, *h1_p, *h2_p, *h3_p;
    cudaGetSymbolAddress(&vs_p, g_vs);
    cudaGetSymbolAddress(&h1_p, g_h1);
    cudaGetSymbolAddress(&h2_p, g_h2);
    cudaGetSymbolAddress(&h3_p, g_h3);
    float* vs = (float*)vs_p;
    float* h1 = (float*)h1_p;
    float* h2 = (float*)h2_p;
    float* h3 = (float*)h3_p;

    // conv1: CIN=1, COUT_BLK=32, NSPLIT=1, CHUNK=1
    constexpr int SM1 = (1*9*32   + 1*18*34) * 4;    //  3600 B
    // conv2: CIN=32, COUT_BLK=32, NSPLIT=2, CHUNK=8
    constexpr int SM2 = (32*9*32  + 8*18*34) * 4;    // 56448 B
    // conv3: CIN=64, COUT_BLK=32, NSPLIT=1, CHUNK=8
    constexpr int SM3 = (64*9*32  + 8*18*34) * 4;    // 93312 B
    // conv4
    constexpr int SM4 = (288      + 8*18*34) * 4;    // 20736 B

    cudaFuncSetAttribute(conv3x3_p2_kernel<1,32,1,1,true>,
                         cudaFuncAttributeMaxDynamicSharedMemorySize, SM1);
    cudaFuncSetAttribute(conv3x3_p2_kernel<32,32,2,8,true>,
                         cudaFuncAttributeMaxDynamicSharedMemorySize, SM2);
    cudaFuncSetAttribute(conv3x3_p2_kernel<64,32,1,8,true>,
                         cudaFuncAttributeMaxDynamicSharedMemorySize, SM3);
    cudaFuncSetAttribute(conv4_kernel,
                         cudaFuncAttributeMaxDynamicSharedMemorySize, SM4);

    // 1) elementwise
    ew_kernel<<<(BHW + 255)/256, 256>>>(inputs, H0, C0, c2, sf, out);

    dim3 blk(16, 16);

    // 2) conv1: 1->32, relu
    conv3x3_p2_kernel<1,32,1,1,true>
        <<<dim3(8,16,BATCH), blk, SM1>>>(vs, w1, b1, h1);
    // 3) conv2: 32->64, relu (co split across 2 blocks)
    conv3x3_p2_kernel<32,32,2,8,true>
        <<<dim3(8,16,BATCH*2), blk, SM2>>>(h1, w2, b2, h2);
    // 4) conv3: 64->32, relu
    conv3x3_p2_kernel<64,32,1,8,true>
        <<<dim3(8,16,BATCH), blk, SM3>>>(h2, w3, b3, h3);
    // 5) conv4 + epilogue
    conv4_kernel<<<dim3(8,16,BATCH), blk, SM4>>>(h3, w4, b4, sf, out);
}